// round 3
// baseline (speedup 1.0000x reference)
#include <cuda_runtime.h>
#include <cuda_bf16.h>

// ---------------------------------------------------------------------------
// GAT_25383256720122 : 2-layer GAT + pooling + MLP head, fp32 baseline.
// NOTE: edge_index / batch arrive as int32 (JAX default x64-disabled downcast).
// ---------------------------------------------------------------------------

#define N_NODES 100000
#define E_EDGES 1600000
#define E_TOT   (E_EDGES + N_NODES)   // 1,700,000 (self loops appended)
#define F_INPUT 256
#define HD      128
#define G_GR    128
#define NCLS    10

// ------------------------- device scratch ----------------------------------
__device__ float d_h[N_NODES * HD];      // node features (layer input/output)
__device__ float d_g[N_NODES * HD];      // linear-transformed features
__device__ float d_hsum[N_NODES * HD];   // h0 + h1 + h2 running sum
__device__ float d_as[N_NODES * 2];
__device__ float d_ad[N_NODES * 2];
__device__ float d_ew[E_TOT * 2];        // exp(leakyrelu(e)) per head
__device__ int   d_src[E_TOT];
__device__ int   d_dst[E_TOT];
__device__ int   d_eidx[E_TOT];          // edge ids sorted by dst (CSR)
__device__ int   d_deg[N_NODES];
__device__ int   d_rowstart[N_NODES + 1];
__device__ int   d_cursor[N_NODES];
__device__ float d_reprs[G_GR * HD];

// ------------------------- prep --------------------------------------------
__global__ void prep_kernel(const int* __restrict__ ei) {
    int i = blockIdx.x * blockDim.x + threadIdx.x;
    if (i < E_EDGES) {
        d_src[i] = ei[i];
        d_dst[i] = ei[E_EDGES + i];
    } else if (i < E_TOT) {
        int n = i - E_EDGES;
        d_src[i] = n;
        d_dst[i] = n;
    }
    if (i < N_NODES) d_deg[i] = 0;
    if (i < G_GR * HD) d_reprs[i] = 0.f;
}

__global__ void hist_kernel() {
    int i = blockIdx.x * blockDim.x + threadIdx.x;
    if (i < E_TOT) atomicAdd(&d_deg[d_dst[i]], 1);
}

// single-block exclusive scan over deg -> rowstart, cursor
__global__ __launch_bounds__(1024) void scan_kernel() {
    __shared__ int warp_sums[32];
    __shared__ int s_carry;
    int tid = threadIdx.x, lane = tid & 31, wid = tid >> 5;
    if (tid == 0) { s_carry = 0; d_rowstart[0] = 0; }
    __syncthreads();
    for (int base = 0; base < N_NODES; base += 1024) {
        int i = base + tid;
        int v = (i < N_NODES) ? d_deg[i] : 0;
        int x = v;
        #pragma unroll
        for (int o = 1; o < 32; o <<= 1) {
            int y = __shfl_up_sync(0xffffffffu, x, o);
            if (lane >= o) x += y;
        }
        if (lane == 31) warp_sums[wid] = x;
        __syncthreads();
        if (wid == 0) {
            int w = warp_sums[lane];
            #pragma unroll
            for (int o = 1; o < 32; o <<= 1) {
                int y = __shfl_up_sync(0xffffffffu, w, o);
                if (lane >= o) w += y;
            }
            warp_sums[lane] = w;
        }
        __syncthreads();
        int incl = x + (wid > 0 ? warp_sums[wid - 1] : 0);
        int carry = s_carry;
        if (i < N_NODES) {
            d_rowstart[i + 1] = carry + incl;
            d_cursor[i]       = carry + incl - v;   // exclusive
        }
        __syncthreads();
        if (tid == 1023) s_carry = carry + incl;
        __syncthreads();
    }
}

__global__ void scatter_kernel() {
    int i = blockIdx.x * blockDim.x + threadIdx.x;
    if (i < E_TOT) {
        int p = atomicAdd(&d_cursor[d_dst[i]], 1);
        d_eidx[p] = i;
    }
}

// ------------------------- SGEMM (C[M,128] = A[M,K] @ B[K,128]) ------------
// mode bit0: +bias, bit1: relu, bit2: also write Caux
__global__ __launch_bounds__(256) void sgemm_kernel(
    const float* __restrict__ A, const float* __restrict__ B,
    const float* __restrict__ bias, float* __restrict__ C,
    float* __restrict__ Caux, int M, int K, int mode)
{
    __shared__ float As[8][128];
    __shared__ float Bs[8][128];
    const int tid = threadIdx.x;
    const int tr = tid >> 4;          // 0..15 (row group)
    const int tc = tid & 15;          // 0..15 (col group)
    const int row0 = blockIdx.x * 128;
    const int lr = tid >> 1;          // 0..127
    const int lc = (tid & 1) << 2;    // 0 or 4
    const int br = tid >> 5;          // 0..7
    const int bc = (tid & 31) << 2;   // 0..124

    float acc[8][8];
    #pragma unroll
    for (int i = 0; i < 8; i++)
        #pragma unroll
        for (int j = 0; j < 8; j++) acc[i][j] = 0.f;

    const int arow = row0 + lr;
    for (int k0 = 0; k0 < K; k0 += 8) {
        float4 av = make_float4(0.f, 0.f, 0.f, 0.f);
        if (arow < M) av = *(const float4*)(A + (size_t)arow * K + k0 + lc);
        As[lc + 0][lr] = av.x;
        As[lc + 1][lr] = av.y;
        As[lc + 2][lr] = av.z;
        As[lc + 3][lr] = av.w;
        *(float4*)&Bs[br][bc] = *(const float4*)(B + (size_t)(k0 + br) * 128 + bc);
        __syncthreads();
        #pragma unroll
        for (int kk = 0; kk < 8; kk++) {
            float4 a0 = *(const float4*)&As[kk][tr * 8];
            float4 a1 = *(const float4*)&As[kk][tr * 8 + 4];
            float4 b0 = *(const float4*)&Bs[kk][tc * 8];
            float4 b1 = *(const float4*)&Bs[kk][tc * 8 + 4];
            float a[8] = {a0.x, a0.y, a0.z, a0.w, a1.x, a1.y, a1.z, a1.w};
            float b[8] = {b0.x, b0.y, b0.z, b0.w, b1.x, b1.y, b1.z, b1.w};
            #pragma unroll
            for (int i = 0; i < 8; i++)
                #pragma unroll
                for (int j = 0; j < 8; j++) acc[i][j] += a[i] * b[j];
        }
        __syncthreads();
    }
    #pragma unroll
    for (int i = 0; i < 8; i++) {
        int r = row0 + tr * 8 + i;
        if (r < M) {
            #pragma unroll
            for (int j = 0; j < 8; j++) {
                int c = tc * 8 + j;
                float v = acc[i][j];
                if (mode & 1) v += bias[c];
                if (mode & 2) v = fmaxf(v, 0.f);
                C[(size_t)r * 128 + c] = v;
                if (mode & 4) Caux[(size_t)r * 128 + c] = v;
            }
        }
    }
}

// ------------------------- per-node attention dots --------------------------
__global__ __launch_bounds__(256) void alpha_kernel(
    const float* __restrict__ asrc, const float* __restrict__ adst)
{
    int warp = (blockIdx.x * blockDim.x + threadIdx.x) >> 5;
    if (warp >= N_NODES) return;
    int lane = threadIdx.x & 31;
    float4 gv = ((const float4*)&d_g[(size_t)warp * HD])[lane];
    float4 s4 = ((const float4*)asrc)[lane];
    float4 a4 = ((const float4*)adst)[lane];
    float ps = gv.x * s4.x + gv.y * s4.y + gv.z * s4.z + gv.w * s4.w;
    float pd = gv.x * a4.x + gv.y * a4.y + gv.z * a4.z + gv.w * a4.w;
    #pragma unroll
    for (int o = 8; o > 0; o >>= 1) {
        ps += __shfl_down_sync(0xffffffffu, ps, o, 16);
        pd += __shfl_down_sync(0xffffffffu, pd, o, 16);
    }
    if ((lane & 15) == 0) {
        int h = lane >> 4;
        d_as[warp * 2 + h] = ps;
        d_ad[warp * 2 + h] = pd;
    }
}

// ------------------------- edge weights ------------------------------------
__global__ void edge_kernel() {
    int e = blockIdx.x * blockDim.x + threadIdx.x;
    if (e >= E_TOT) return;
    int s = d_src[e], d = d_dst[e];
    float2 a = *(const float2*)&d_as[s * 2];
    float2 b = *(const float2*)&d_ad[d * 2];
    float v0 = a.x + b.x;
    float v1 = a.y + b.y;
    v0 = v0 > 0.f ? v0 : 0.2f * v0;
    v1 = v1 > 0.f ? v1 : 0.2f * v1;
    // bounded logits -> softmax without max-subtraction is exact
    float2 w = make_float2(__expf(v0), __expf(v1));
    *(float2*)&d_ew[e * 2] = w;
}

// ------------------------- per-dst aggregation (CSR) ------------------------
__global__ __launch_bounds__(128) void agg_kernel(const float* __restrict__ bias) {
    int n = blockIdx.x;
    int t = threadIdx.x;
    int head = t >> 6;
    int start = d_rowstart[n], end = d_rowstart[n + 1];
    __shared__ int   s_src[128];
    __shared__ float s_w0[128];
    __shared__ float s_w1[128];
    float acc = 0.f, wsum = 0.f;
    for (int base = start; base < end; base += 128) {
        int cnt = min(128, end - base);
        if (t < cnt) {
            int e = d_eidx[base + t];
            s_src[t] = d_src[e];
            float2 w = *(const float2*)&d_ew[e * 2];
            s_w0[t] = w.x;
            s_w1[t] = w.y;
        }
        __syncthreads();
        for (int i = 0; i < cnt; i++) {
            int s = s_src[i];
            float w = head ? s_w1[i] : s_w0[i];
            acc += d_g[(size_t)s * HD + t] * w;
            wsum += w;
        }
        __syncthreads();
    }
    float out = acc / wsum + bias[t];
    out = fmaxf(out, 0.f);
    d_h[(size_t)n * HD + t] = out;
    d_hsum[(size_t)n * HD + t] += out;
}

// ------------------------- pooling (sorted batch) ---------------------------
__global__ __launch_bounds__(128) void pool_kernel(const int* __restrict__ batch) {
    const int CH = 512;
    int n0 = blockIdx.x * CH;
    int t = threadIdx.x;
    int nend = min(n0 + CH, N_NODES);
    int cnt = nend - n0;
    __shared__ int s_b[CH];
    for (int i = t; i < cnt; i += 128) s_b[i] = batch[n0 + i];
    __syncthreads();
    float acc = 0.f;
    int cur = s_b[0];
    for (int k = 0; k < cnt; k++) {
        int b = s_b[k];
        if (b != cur) {
            atomicAdd(&d_reprs[cur * HD + t], acc);
            acc = 0.f;
            cur = b;
        }
        acc += d_hsum[(size_t)(n0 + k) * HD + t];
    }
    atomicAdd(&d_reprs[cur * HD + t], acc);
}

// ------------------------- final MLP + log_softmax --------------------------
__global__ __launch_bounds__(128) void final_kernel(
    const float* __restrict__ W1, const float* __restrict__ b1,
    const float* __restrict__ W2, const float* __restrict__ b2,
    float* __restrict__ out)
{
    int g = blockIdx.x;
    int t = threadIdx.x;
    __shared__ float s_r[HD];
    __shared__ float s_z[HD];
    __shared__ float s_o[NCLS];
    s_r[t] = d_reprs[g * HD + t];
    __syncthreads();
    float acc = b1[t];
    #pragma unroll 4
    for (int k = 0; k < HD; k++) acc += s_r[k] * W1[k * HD + t];
    s_z[t] = fmaxf(acc, 0.f);
    __syncthreads();
    if (t < NCLS) {
        float a = b2[t];
        #pragma unroll 4
        for (int k = 0; k < HD; k++) a += s_z[k] * W2[k * NCLS + t];
        s_o[t] = a;
    }
    __syncthreads();
    if (t == 0) {
        float m = -1e30f;
        for (int c = 0; c < NCLS; c++) m = fmaxf(m, s_o[c]);
        float sum = 0.f;
        for (int c = 0; c < NCLS; c++) sum += expf(s_o[c] - m);
        float lse = m + logf(sum);
        for (int c = 0; c < NCLS; c++) out[g * NCLS + c] = s_o[c] - lse;
    }
}

// ------------------------- launch ------------------------------------------
extern "C" void kernel_launch(void* const* d_in, const int* in_sizes, int n_in,
                              void* d_out, int out_size)
{
    const float* x       = (const float*)d_in[0];
    const int*   ei      = (const int*)d_in[1];     // int32 (JAX x64 disabled)
    const int*   batch   = (const int*)d_in[2];     // int32
    const float* pre_w   = (const float*)d_in[3];
    const float* pre_b   = (const float*)d_in[4];
    const float* w1      = (const float*)d_in[5];
    const float* asrc1   = (const float*)d_in[6];
    const float* adst1   = (const float*)d_in[7];
    const float* b1      = (const float*)d_in[8];
    const float* w2      = (const float*)d_in[9];
    const float* asrc2   = (const float*)d_in[10];
    const float* adst2   = (const float*)d_in[11];
    const float* b2      = (const float*)d_in[12];
    const float* post_w1 = (const float*)d_in[13];
    const float* post_b1 = (const float*)d_in[14];
    const float* post_w2 = (const float*)d_in[15];
    const float* post_b2 = (const float*)d_in[16];
    float* out = (float*)d_out;

    void *p_h_, *p_g_, *p_hsum_;
    cudaGetSymbolAddress(&p_h_, d_h);
    cudaGetSymbolAddress(&p_g_, d_g);
    cudaGetSymbolAddress(&p_hsum_, d_hsum);
    float* p_h = (float*)p_h_;
    float* p_g = (float*)p_g_;
    float* p_hsum = (float*)p_hsum_;

    const int TPB = 256;
    const int eblocks = (E_TOT + TPB - 1) / TPB;
    const int gemm_blocks = (N_NODES + 127) / 128;

    // graph structure (rebuilt every call: deterministic given inputs)
    prep_kernel<<<eblocks, TPB>>>(ei);
    hist_kernel<<<eblocks, TPB>>>();
    scan_kernel<<<1, 1024>>>();
    scatter_kernel<<<eblocks, TPB>>>();

    // pre layer: h = relu(x@pre_w + pre_b); hsum = h
    sgemm_kernel<<<gemm_blocks, 256>>>(x, pre_w, pre_b, p_h, p_hsum,
                                       N_NODES, F_INPUT, 1 | 2 | 4);

    // GAT layer 1
    sgemm_kernel<<<gemm_blocks, 256>>>(p_h, w1, pre_b, p_g, p_g,
                                       N_NODES, HD, 0);
    alpha_kernel<<<(N_NODES + 7) / 8, 256>>>(asrc1, adst1);
    edge_kernel<<<eblocks, TPB>>>();
    agg_kernel<<<N_NODES, 128>>>(b1);

    // GAT layer 2
    sgemm_kernel<<<gemm_blocks, 256>>>(p_h, w2, pre_b, p_g, p_g,
                                       N_NODES, HD, 0);
    alpha_kernel<<<(N_NODES + 7) / 8, 256>>>(asrc2, adst2);
    edge_kernel<<<eblocks, TPB>>>();
    agg_kernel<<<N_NODES, 128>>>(b2);

    // pooling + head
    pool_kernel<<<(N_NODES + 511) / 512, 128>>>(batch);
    final_kernel<<<G_GR, 128>>>(post_w1, post_b1, post_w2, post_b2, out);
}

// round 7
// speedup vs baseline: 1.5305x; 1.5305x over previous
#include <cuda_runtime.h>
#include <cuda_bf16.h>
#include <cstdint>

// ---------------------------------------------------------------------------
// GAT_25383256720122 : 2-layer GAT + pooling + MLP head.
// R6: mma.sync bf16-split GEMMs (generic sm_103 PTX; tcgen05 unavailable
//     because harness emits compute_103, not compute_103a), fused epilogues,
//     parallel CSR scan, hist fused into prep.
// ---------------------------------------------------------------------------

#define N_NODES 100000
#define E_EDGES 1600000
#define E_TOT   (E_EDGES + N_NODES)
#define F_INPUT 256
#define HD      128
#define G_GR    128
#define NCLS    10
#define NB_SCAN ((N_NODES + 1023) / 1024)   // 98

// ------------------------- device scratch ----------------------------------
__device__ float d_h[N_NODES * HD];
__device__ float d_g[N_NODES * HD];
__device__ float d_hsum[N_NODES * HD];
__device__ float d_as[N_NODES * 2];
__device__ float d_ad[N_NODES * 2];
__device__ float d_ew[E_TOT * 2];
__device__ int   d_src[E_TOT];
__device__ int   d_dst[E_TOT];
__device__ int   d_eidx[E_TOT];
__device__ int   d_deg[N_NODES];
__device__ int   d_rowstart[N_NODES + 1];
__device__ int   d_cursor[N_NODES];
__device__ float d_reprs[G_GR * HD];
__device__ int   d_bsum[NB_SCAN];
__device__ int   d_boff[NB_SCAN];

// ------------------------- helpers -----------------------------------------
__device__ __forceinline__ uint32_t smem_u32(const void* p) {
    uint32_t a;
    asm("{ .reg .u64 t; cvta.to.shared.u64 t, %1; cvt.u32.u64 %0, t; }"
        : "=r"(a) : "l"(p));
    return a;
}

__device__ __forceinline__ void ldsm_x4(uint32_t addr, uint32_t* r) {
    asm volatile("ldmatrix.sync.aligned.m8n8.x4.shared.b16 {%0,%1,%2,%3}, [%4];"
        : "=r"(r[0]), "=r"(r[1]), "=r"(r[2]), "=r"(r[3]) : "r"(addr));
}

__device__ __forceinline__ void mma_bf16(float* c, const uint32_t* a,
                                         const uint32_t* b) {
    asm volatile(
        "mma.sync.aligned.m16n8k16.row.col.f32.bf16.bf16.f32 "
        "{%0,%1,%2,%3}, {%4,%5,%6,%7}, {%8,%9}, {%0,%1,%2,%3};"
        : "+f"(c[0]), "+f"(c[1]), "+f"(c[2]), "+f"(c[3])
        : "r"(a[0]), "r"(a[1]), "r"(a[2]), "r"(a[3]), "r"(b[0]), "r"(b[1]));
}

// smem layout (bytes), pitch 72 bf16 = 144 B
#define PITCH    72
#define OFF_AHI  0
#define OFF_ALO  18432
#define OFF_BHI  36864
#define OFF_BLO  55296
#define OFF_V0   73728
#define OFF_V1   74240
#define SMEM_DYN 74752

// ------------------------- prep (+hist fused) ------------------------------
__global__ void zero_kernel() {
    int i = blockIdx.x * blockDim.x + threadIdx.x;
    if (i < N_NODES) d_deg[i] = 0;
    if (i < G_GR * HD) d_reprs[i] = 0.f;
}

__global__ void prep_hist_kernel(const int* __restrict__ ei) {
    int i = blockIdx.x * blockDim.x + threadIdx.x;
    if (i < E_EDGES) {
        int s = ei[i], d = ei[E_EDGES + i];
        d_src[i] = s;
        d_dst[i] = d;
        atomicAdd(&d_deg[d], 1);
    } else if (i < E_TOT) {
        int n = i - E_EDGES;
        d_src[i] = n;
        d_dst[i] = n;
        atomicAdd(&d_deg[n], 1);
    }
}

// ------------------------- 3-phase scan ------------------------------------
__global__ __launch_bounds__(1024) void scanA_kernel() {
    __shared__ int ws[32];
    int tid = threadIdx.x, lane = tid & 31, wid = tid >> 5;
    int i = blockIdx.x * 1024 + tid;
    int v = (i < N_NODES) ? d_deg[i] : 0;
    #pragma unroll
    for (int o = 16; o > 0; o >>= 1) v += __shfl_down_sync(0xffffffffu, v, o);
    if (lane == 0) ws[wid] = v;
    __syncthreads();
    if (wid == 0) {
        int s = ws[lane];
        #pragma unroll
        for (int o = 16; o > 0; o >>= 1) s += __shfl_down_sync(0xffffffffu, s, o);
        if (lane == 0) d_bsum[blockIdx.x] = s;
    }
}

__global__ void scanB_kernel() {
    if (threadIdx.x == 0) {
        int run = 0;
        for (int b = 0; b < NB_SCAN; b++) { d_boff[b] = run; run += d_bsum[b]; }
        d_rowstart[0] = 0;
    }
}

__global__ __launch_bounds__(1024) void scanC_kernel() {
    __shared__ int ws[32];
    int tid = threadIdx.x, lane = tid & 31, wid = tid >> 5;
    int i = blockIdx.x * 1024 + tid;
    int v = (i < N_NODES) ? d_deg[i] : 0;
    int x = v;
    #pragma unroll
    for (int o = 1; o < 32; o <<= 1) {
        int y = __shfl_up_sync(0xffffffffu, x, o);
        if (lane >= o) x += y;
    }
    if (lane == 31) ws[wid] = x;
    __syncthreads();
    if (wid == 0) {
        int w = ws[lane];
        #pragma unroll
        for (int o = 1; o < 32; o <<= 1) {
            int y = __shfl_up_sync(0xffffffffu, w, o);
            if (lane >= o) w += y;
        }
        ws[lane] = w;
    }
    __syncthreads();
    int incl = x + (wid > 0 ? ws[wid - 1] : 0) + d_boff[blockIdx.x];
    if (i < N_NODES) {
        d_rowstart[i + 1] = incl;
        d_cursor[i]       = incl - v;
    }
}

__global__ void scatter_kernel() {
    int i = blockIdx.x * blockDim.x + threadIdx.x;
    if (i < E_TOT) {
        int p = atomicAdd(&d_cursor[d_dst[i]], 1);
        d_eidx[p] = i;
    }
}

// ------------------------- mma.sync GEMM -----------------------------------
// C[M,128] = A[M,K] @ W[K,128], bf16 hi/lo split (3 mma terms).
// mode 0: C = relu(A@W + vec0), Caux = C.
// mode 1: C = A@W raw; fused alpha dots: as_out/ad_out [M,2].
__global__ __launch_bounds__(256) void mma_gemm_kernel(
    const float* __restrict__ A, int K,
    const float* __restrict__ W,
    const float* __restrict__ vec0, const float* __restrict__ vec1,
    float* __restrict__ C, float* __restrict__ Caux,
    float* __restrict__ as_out, float* __restrict__ ad_out,
    int M, int mode)
{
    extern __shared__ char sm[];
    const uint32_t sb = smem_u32(sm);
    float* sv0 = (float*)(sm + OFF_V0);
    float* sv1 = (float*)(sm + OFF_V1);

    const int tid = threadIdx.x;
    const int w = tid >> 5;
    const int lane = tid & 31;
    const int mr = w >> 1;          // 0..3 : warp M-row
    const int nc = w & 1;           // 0..1 : warp N-col (== attention head)
    const int row0 = blockIdx.x * 128;
    const int g = lane >> 2, tg = lane & 3;

    if (tid < 128) {
        sv0[tid] = vec0 ? vec0[tid] : 0.f;
        sv1[tid] = vec1 ? vec1[tid] : 0.f;
    }

    float acc[2][8][4];
    #pragma unroll
    for (int mt = 0; mt < 2; mt++)
        #pragma unroll
        for (int nt = 0; nt < 8; nt++)
            #pragma unroll
            for (int q = 0; q < 4; q++) acc[mt][nt][q] = 0.f;

    const int nchunk = K >> 6;
    for (int ch = 0; ch < nchunk; ch++) {
        const int k0 = ch << 6;
        // ---- load+split A: 128 rows x 64 cols ----
        {
            int c4 = (tid & 15) * 4;
            int rb = tid >> 4;
            #pragma unroll
            for (int i = 0; i < 8; i++) {
                int r = rb + i * 16;
                int gr = row0 + r;
                float4 v = make_float4(0.f, 0.f, 0.f, 0.f);
                if (gr < M) v = *(const float4*)(A + (size_t)gr * K + k0 + c4);
                __nv_bfloat162 hA = __floats2bfloat162_rn(v.x, v.y);
                __nv_bfloat162 hB = __floats2bfloat162_rn(v.z, v.w);
                __nv_bfloat162 lA = __floats2bfloat162_rn(
                    v.x - __bfloat162float(hA.x), v.y - __bfloat162float(hA.y));
                __nv_bfloat162 lB = __floats2bfloat162_rn(
                    v.z - __bfloat162float(hB.x), v.w - __bfloat162float(hB.y));
                uint32_t off = (uint32_t)(r * (PITCH * 2) + c4 * 2);
                *(uint2*)(sm + OFF_AHI + off) =
                    make_uint2(*(uint32_t*)&hA, *(uint32_t*)&hB);
                *(uint2*)(sm + OFF_ALO + off) =
                    make_uint2(*(uint32_t*)&lA, *(uint32_t*)&lB);
            }
        }
        // ---- load+split B: W[k0..k0+63][n] -> Bs[n][k] ----
        {
            int n = tid >> 1;
            int kh = (tid & 1) * 32;
            #pragma unroll
            for (int kk = 0; kk < 32; kk += 2) {
                float v0 = W[(size_t)(k0 + kh + kk) * 128 + n];
                float v1 = W[(size_t)(k0 + kh + kk + 1) * 128 + n];
                __nv_bfloat162 h2 = __floats2bfloat162_rn(v0, v1);
                __nv_bfloat162 l2 = __floats2bfloat162_rn(
                    v0 - __bfloat162float(h2.x), v1 - __bfloat162float(h2.y));
                uint32_t off = (uint32_t)(n * (PITCH * 2) + (kh + kk) * 2);
                *(uint32_t*)(sm + OFF_BHI + off) = *(uint32_t*)&h2;
                *(uint32_t*)(sm + OFF_BLO + off) = *(uint32_t*)&l2;
            }
        }
        __syncthreads();

        // ---- compute: 4 k-steps of 16 ----
        #pragma unroll
        for (int ks = 0; ks < 4; ks++) {
            uint32_t ah[2][4], al[2][4];
            #pragma unroll
            for (int mt = 0; mt < 2; mt++) {
                uint32_t aoff = (uint32_t)(
                    (mr * 32 + mt * 16 + (lane & 15)) * (PITCH * 2)
                    + (ks * 16 + (lane >> 4) * 8) * 2);
                ldsm_x4(sb + OFF_AHI + aoff, ah[mt]);
                ldsm_x4(sb + OFF_ALO + aoff, al[mt]);
            }
            #pragma unroll
            for (int np = 0; np < 4; np++) {
                int n_idx = nc * 64 + np * 16 + (lane & 7) + ((lane >> 4) & 1) * 8;
                int koff = ks * 16 + ((lane >> 3) & 1) * 8;
                uint32_t boff = (uint32_t)(n_idx * (PITCH * 2) + koff * 2);
                uint32_t bh[4], bl[4];
                ldsm_x4(sb + OFF_BHI + boff, bh);
                ldsm_x4(sb + OFF_BLO + boff, bl);
                #pragma unroll
                for (int mt = 0; mt < 2; mt++) {
                    mma_bf16(acc[mt][np * 2],     ah[mt], bh);
                    mma_bf16(acc[mt][np * 2],     ah[mt], bl);
                    mma_bf16(acc[mt][np * 2],     al[mt], bh);
                    mma_bf16(acc[mt][np * 2 + 1], ah[mt], bh + 2);
                    mma_bf16(acc[mt][np * 2 + 1], ah[mt], bl + 2);
                    mma_bf16(acc[mt][np * 2 + 1], al[mt], bh + 2);
                }
            }
        }
        __syncthreads();
    }

    // ---- epilogue ----
    #pragma unroll
    for (int mt = 0; mt < 2; mt++) {
        int grA = row0 + mr * 32 + mt * 16 + g;
        int grB = grA + 8;
        if (mode == 0) {
            #pragma unroll
            for (int nt = 0; nt < 8; nt++) {
                int col = nc * 64 + nt * 8 + 2 * tg;
                float2 vA = make_float2(
                    fmaxf(acc[mt][nt][0] + sv0[col], 0.f),
                    fmaxf(acc[mt][nt][1] + sv0[col + 1], 0.f));
                float2 vB = make_float2(
                    fmaxf(acc[mt][nt][2] + sv0[col], 0.f),
                    fmaxf(acc[mt][nt][3] + sv0[col + 1], 0.f));
                if (grA < M) {
                    *(float2*)(C + (size_t)grA * 128 + col) = vA;
                    *(float2*)(Caux + (size_t)grA * 128 + col) = vA;
                }
                if (grB < M) {
                    *(float2*)(C + (size_t)grB * 128 + col) = vB;
                    *(float2*)(Caux + (size_t)grB * 128 + col) = vB;
                }
            }
        } else {
            float psA = 0.f, pdA = 0.f, psB = 0.f, pdB = 0.f;
            #pragma unroll
            for (int nt = 0; nt < 8; nt++) {
                int col = nc * 64 + nt * 8 + 2 * tg;
                float c0 = acc[mt][nt][0], c1 = acc[mt][nt][1];
                float c2 = acc[mt][nt][2], c3 = acc[mt][nt][3];
                float s0 = sv0[col], s1 = sv0[col + 1];
                float t0 = sv1[col], t1 = sv1[col + 1];
                psA += c0 * s0 + c1 * s1;
                pdA += c0 * t0 + c1 * t1;
                psB += c2 * s0 + c3 * s1;
                pdB += c2 * t0 + c3 * t1;
                if (grA < M) *(float2*)(C + (size_t)grA * 128 + col) = make_float2(c0, c1);
                if (grB < M) *(float2*)(C + (size_t)grB * 128 + col) = make_float2(c2, c3);
            }
            #pragma unroll
            for (int o = 1; o < 4; o <<= 1) {
                psA += __shfl_xor_sync(0xffffffffu, psA, o);
                pdA += __shfl_xor_sync(0xffffffffu, pdA, o);
                psB += __shfl_xor_sync(0xffffffffu, psB, o);
                pdB += __shfl_xor_sync(0xffffffffu, pdB, o);
            }
            if (tg == 0) {
                if (grA < M) {
                    as_out[grA * 2 + nc] = psA;
                    ad_out[grA * 2 + nc] = pdA;
                }
                if (grB < M) {
                    as_out[grB * 2 + nc] = psB;
                    ad_out[grB * 2 + nc] = pdB;
                }
            }
        }
    }
}

// ------------------------- edge weights ------------------------------------
__global__ void edge_kernel() {
    int e = blockIdx.x * blockDim.x + threadIdx.x;
    if (e >= E_TOT) return;
    int s = d_src[e], d = d_dst[e];
    float2 a = *(const float2*)&d_as[s * 2];
    float2 b = *(const float2*)&d_ad[d * 2];
    float v0 = a.x + b.x;
    float v1 = a.y + b.y;
    v0 = v0 > 0.f ? v0 : 0.2f * v0;
    v1 = v1 > 0.f ? v1 : 0.2f * v1;
    float2 w = make_float2(__expf(v0), __expf(v1));
    *(float2*)&d_ew[e * 2] = w;
}

// ------------------------- per-dst aggregation (CSR) ------------------------
__global__ __launch_bounds__(128) void agg_kernel(const float* __restrict__ bias) {
    int n = blockIdx.x;
    int t = threadIdx.x;
    int head = t >> 6;
    int start = d_rowstart[n], end = d_rowstart[n + 1];
    __shared__ int   s_src[128];
    __shared__ float s_w0[128];
    __shared__ float s_w1[128];
    float acc = 0.f, wsum = 0.f;
    for (int base = start; base < end; base += 128) {
        int cnt = min(128, end - base);
        if (t < cnt) {
            int e = d_eidx[base + t];
            s_src[t] = d_src[e];
            float2 w = *(const float2*)&d_ew[e * 2];
            s_w0[t] = w.x;
            s_w1[t] = w.y;
        }
        __syncthreads();
        for (int i = 0; i < cnt; i++) {
            int s = s_src[i];
            float w = head ? s_w1[i] : s_w0[i];
            acc += d_g[(size_t)s * HD + t] * w;
            wsum += w;
        }
        __syncthreads();
    }
    float out = acc / wsum + bias[t];
    out = fmaxf(out, 0.f);
    d_h[(size_t)n * HD + t] = out;
    d_hsum[(size_t)n * HD + t] += out;
}

// ------------------------- pooling (sorted batch) ---------------------------
__global__ __launch_bounds__(128) void pool_kernel(const int* __restrict__ batch) {
    const int CH = 512;
    int n0 = blockIdx.x * CH;
    int t = threadIdx.x;
    int nend = min(n0 + CH, N_NODES);
    int cnt = nend - n0;
    __shared__ int s_b[CH];
    for (int i = t; i < cnt; i += 128) s_b[i] = batch[n0 + i];
    __syncthreads();
    float acc = 0.f;
    int cur = s_b[0];
    for (int k = 0; k < cnt; k++) {
        int b = s_b[k];
        if (b != cur) {
            atomicAdd(&d_reprs[cur * HD + t], acc);
            acc = 0.f;
            cur = b;
        }
        acc += d_hsum[(size_t)(n0 + k) * HD + t];
    }
    atomicAdd(&d_reprs[cur * HD + t], acc);
}

// ------------------------- final MLP + log_softmax --------------------------
__global__ __launch_bounds__(128) void final_kernel(
    const float* __restrict__ W1, const float* __restrict__ b1,
    const float* __restrict__ W2, const float* __restrict__ b2,
    float* __restrict__ out)
{
    int g = blockIdx.x;
    int t = threadIdx.x;
    __shared__ float s_r[HD];
    __shared__ float s_z[HD];
    __shared__ float s_o[NCLS];
    s_r[t] = d_reprs[g * HD + t];
    __syncthreads();
    float acc = b1[t];
    #pragma unroll 4
    for (int k = 0; k < HD; k++) acc += s_r[k] * W1[k * HD + t];
    s_z[t] = fmaxf(acc, 0.f);
    __syncthreads();
    if (t < NCLS) {
        float a = b2[t];
        #pragma unroll 4
        for (int k = 0; k < HD; k++) a += s_z[k] * W2[k * NCLS + t];
        s_o[t] = a;
    }
    __syncthreads();
    if (t == 0) {
        float m = -1e30f;
        for (int c = 0; c < NCLS; c++) m = fmaxf(m, s_o[c]);
        float sum = 0.f;
        for (int c = 0; c < NCLS; c++) sum += expf(s_o[c] - m);
        float lse = m + logf(sum);
        for (int c = 0; c < NCLS; c++) out[g * NCLS + c] = s_o[c] - lse;
    }
}

// ------------------------- launch ------------------------------------------
extern "C" void kernel_launch(void* const* d_in, const int* in_sizes, int n_in,
                              void* d_out, int out_size)
{
    const float* x       = (const float*)d_in[0];
    const int*   ei      = (const int*)d_in[1];
    const int*   batch   = (const int*)d_in[2];
    const float* pre_w   = (const float*)d_in[3];
    const float* pre_b   = (const float*)d_in[4];
    const float* w1      = (const float*)d_in[5];
    const float* asrc1   = (const float*)d_in[6];
    const float* adst1   = (const float*)d_in[7];
    const float* b1      = (const float*)d_in[8];
    const float* w2      = (const float*)d_in[9];
    const float* asrc2   = (const float*)d_in[10];
    const float* adst2   = (const float*)d_in[11];
    const float* b2      = (const float*)d_in[12];
    const float* post_w1 = (const float*)d_in[13];
    const float* post_b1 = (const float*)d_in[14];
    const float* post_w2 = (const float*)d_in[15];
    const float* post_b2 = (const float*)d_in[16];
    float* out = (float*)d_out;

    void *p_h_, *p_g_, *p_hsum_, *p_as_, *p_ad_;
    cudaGetSymbolAddress(&p_h_, d_h);
    cudaGetSymbolAddress(&p_g_, d_g);
    cudaGetSymbolAddress(&p_hsum_, d_hsum);
    cudaGetSymbolAddress(&p_as_, d_as);
    cudaGetSymbolAddress(&p_ad_, d_ad);
    float* p_h = (float*)p_h_;
    float* p_g = (float*)p_g_;
    float* p_hsum = (float*)p_hsum_;
    float* p_as = (float*)p_as_;
    float* p_ad = (float*)p_ad_;

    cudaFuncSetAttribute(mma_gemm_kernel,
                         cudaFuncAttributeMaxDynamicSharedMemorySize, SMEM_DYN);

    const int TPB = 256;
    const int eblocks = (E_TOT + TPB - 1) / TPB;
    const int gb = (N_NODES + 127) / 128;

    zero_kernel<<<(N_NODES + TPB - 1) / TPB, TPB>>>();
    prep_hist_kernel<<<eblocks, TPB>>>(ei);
    scanA_kernel<<<NB_SCAN, 1024>>>();
    scanB_kernel<<<1, 32>>>();
    scanC_kernel<<<NB_SCAN, 1024>>>();
    scatter_kernel<<<eblocks, TPB>>>();

    // pre layer: h = relu(x@pre_w + pre_b); hsum = h
    mma_gemm_kernel<<<gb, 256, SMEM_DYN>>>(x, F_INPUT, pre_w, pre_b, nullptr,
                                           p_h, p_hsum, nullptr, nullptr,
                                           N_NODES, 0);

    // GAT layer 1
    mma_gemm_kernel<<<gb, 256, SMEM_DYN>>>(p_h, HD, w1, asrc1, adst1,
                                           p_g, nullptr, p_as, p_ad,
                                           N_NODES, 1);
    edge_kernel<<<eblocks, TPB>>>();
    agg_kernel<<<N_NODES, 128>>>(b1);

    // GAT layer 2
    mma_gemm_kernel<<<gb, 256, SMEM_DYN>>>(p_h, HD, w2, asrc2, adst2,
                                           p_g, nullptr, p_as, p_ad,
                                           N_NODES, 1);
    edge_kernel<<<eblocks, TPB>>>();
    agg_kernel<<<N_NODES, 128>>>(b2);

    // pooling + head
    pool_kernel<<<(N_NODES + 511) / 512, 128>>>(batch);
    final_kernel<<<G_GR, 128>>>(post_w1, post_b1, post_w2, post_b2, out);
}

// round 8
// speedup vs baseline: 1.9983x; 1.3057x over previous
#include <cuda_runtime.h>
#include <cuda_bf16.h>
#include <cstdint>

// ---------------------------------------------------------------------------
// GAT_25383256720122 : 2-layer GAT + pooling + MLP head.
// R7: edge-weight computation fused into agg (edge_kernel deleted),
//     CSR stores src ids directly (no eidx indirection),
//     scanB deleted (per-block prefix inside scanC).
// ---------------------------------------------------------------------------

#define N_NODES 100000
#define E_EDGES 1600000
#define E_TOT   (E_EDGES + N_NODES)
#define F_INPUT 256
#define HD      128
#define G_GR    128
#define NCLS    10
#define NB_SCAN ((N_NODES + 1023) / 1024)   // 98

// ------------------------- device scratch ----------------------------------
__device__ float d_h[N_NODES * HD];
__device__ float d_g[N_NODES * HD];
__device__ float d_hsum[N_NODES * HD];
__device__ float d_as[N_NODES * 2];
__device__ float d_ad[N_NODES * 2];
__device__ int   d_src[E_TOT];
__device__ int   d_dst[E_TOT];
__device__ int   d_esrc[E_TOT];          // CSR payload: src id per slot
__device__ int   d_deg[N_NODES];
__device__ int   d_rowstart[N_NODES + 1];
__device__ int   d_cursor[N_NODES];
__device__ float d_reprs[G_GR * HD];
__device__ int   d_bsum[NB_SCAN];

// ------------------------- helpers -----------------------------------------
__device__ __forceinline__ uint32_t smem_u32(const void* p) {
    uint32_t a;
    asm("{ .reg .u64 t; cvta.to.shared.u64 t, %1; cvt.u32.u64 %0, t; }"
        : "=r"(a) : "l"(p));
    return a;
}

__device__ __forceinline__ void ldsm_x4(uint32_t addr, uint32_t* r) {
    asm volatile("ldmatrix.sync.aligned.m8n8.x4.shared.b16 {%0,%1,%2,%3}, [%4];"
        : "=r"(r[0]), "=r"(r[1]), "=r"(r[2]), "=r"(r[3]) : "r"(addr));
}

__device__ __forceinline__ void mma_bf16(float* c, const uint32_t* a,
                                         const uint32_t* b) {
    asm volatile(
        "mma.sync.aligned.m16n8k16.row.col.f32.bf16.bf16.f32 "
        "{%0,%1,%2,%3}, {%4,%5,%6,%7}, {%8,%9}, {%0,%1,%2,%3};"
        : "+f"(c[0]), "+f"(c[1]), "+f"(c[2]), "+f"(c[3])
        : "r"(a[0]), "r"(a[1]), "r"(a[2]), "r"(a[3]), "r"(b[0]), "r"(b[1]));
}

// smem layout (bytes), pitch 72 bf16 = 144 B
#define PITCH    72
#define OFF_AHI  0
#define OFF_ALO  18432
#define OFF_BHI  36864
#define OFF_BLO  55296
#define OFF_V0   73728
#define OFF_V1   74240
#define SMEM_DYN 74752

// ------------------------- prep (+hist fused) ------------------------------
__global__ void zero_kernel() {
    int i = blockIdx.x * blockDim.x + threadIdx.x;
    if (i < N_NODES) d_deg[i] = 0;
    if (i < G_GR * HD) d_reprs[i] = 0.f;
}

__global__ void prep_hist_kernel(const int* __restrict__ ei) {
    int i = blockIdx.x * blockDim.x + threadIdx.x;
    if (i < E_EDGES) {
        int s = ei[i], d = ei[E_EDGES + i];
        d_src[i] = s;
        d_dst[i] = d;
        atomicAdd(&d_deg[d], 1);
    } else if (i < E_TOT) {
        int n = i - E_EDGES;
        d_src[i] = n;
        d_dst[i] = n;
        atomicAdd(&d_deg[n], 1);
    }
}

// ------------------------- 2-phase scan ------------------------------------
__global__ __launch_bounds__(1024) void scanA_kernel() {
    __shared__ int ws[32];
    int tid = threadIdx.x, lane = tid & 31, wid = tid >> 5;
    int i = blockIdx.x * 1024 + tid;
    int v = (i < N_NODES) ? d_deg[i] : 0;
    #pragma unroll
    for (int o = 16; o > 0; o >>= 1) v += __shfl_down_sync(0xffffffffu, v, o);
    if (lane == 0) ws[wid] = v;
    __syncthreads();
    if (wid == 0) {
        int s = ws[lane];
        #pragma unroll
        for (int o = 16; o > 0; o >>= 1) s += __shfl_down_sync(0xffffffffu, s, o);
        if (lane == 0) d_bsum[blockIdx.x] = s;
    }
}

__global__ __launch_bounds__(1024) void scanC_kernel() {
    __shared__ int ws[32];
    __shared__ int s_off;
    int tid = threadIdx.x, lane = tid & 31, wid = tid >> 5;
    // block offset: prefix over preceding block sums (<=97 entries)
    if (tid < 32) {
        int tot = 0;
        for (int j = tid; j < blockIdx.x; j += 32) tot += d_bsum[j];
        #pragma unroll
        for (int o = 16; o > 0; o >>= 1)
            tot += __shfl_down_sync(0xffffffffu, tot, o);
        if (tid == 0) s_off = tot;
    }
    int i = blockIdx.x * 1024 + tid;
    int v = (i < N_NODES) ? d_deg[i] : 0;
    int x = v;
    #pragma unroll
    for (int o = 1; o < 32; o <<= 1) {
        int y = __shfl_up_sync(0xffffffffu, x, o);
        if (lane >= o) x += y;
    }
    if (lane == 31) ws[wid] = x;
    __syncthreads();
    if (wid == 0) {
        int w = ws[lane];
        #pragma unroll
        for (int o = 1; o < 32; o <<= 1) {
            int y = __shfl_up_sync(0xffffffffu, w, o);
            if (lane >= o) w += y;
        }
        ws[lane] = w;
    }
    __syncthreads();
    int incl = x + (wid > 0 ? ws[wid - 1] : 0) + s_off;
    if (i < N_NODES) {
        d_rowstart[i + 1] = incl;
        d_cursor[i]       = incl - v;
    }
    if (i == 0) d_rowstart[0] = 0;
}

__global__ void scatter_kernel() {
    int i = blockIdx.x * blockDim.x + threadIdx.x;
    if (i < E_TOT) {
        int p = atomicAdd(&d_cursor[d_dst[i]], 1);
        d_esrc[p] = d_src[i];
    }
}

// ------------------------- mma.sync GEMM -----------------------------------
// C[M,128] = A[M,K] @ W[K,128], bf16 hi/lo split (3 mma terms).
// mode 0: C = relu(A@W + vec0), Caux = C.
// mode 1: C = A@W raw; fused alpha dots: as_out/ad_out [M,2].
__global__ __launch_bounds__(256) void mma_gemm_kernel(
    const float* __restrict__ A, int K,
    const float* __restrict__ W,
    const float* __restrict__ vec0, const float* __restrict__ vec1,
    float* __restrict__ C, float* __restrict__ Caux,
    float* __restrict__ as_out, float* __restrict__ ad_out,
    int M, int mode)
{
    extern __shared__ char sm[];
    const uint32_t sb = smem_u32(sm);
    float* sv0 = (float*)(sm + OFF_V0);
    float* sv1 = (float*)(sm + OFF_V1);

    const int tid = threadIdx.x;
    const int w = tid >> 5;
    const int lane = tid & 31;
    const int mr = w >> 1;          // 0..3 : warp M-row
    const int nc = w & 1;           // 0..1 : warp N-col (== attention head)
    const int row0 = blockIdx.x * 128;
    const int g = lane >> 2, tg = lane & 3;

    if (tid < 128) {
        sv0[tid] = vec0 ? vec0[tid] : 0.f;
        sv1[tid] = vec1 ? vec1[tid] : 0.f;
    }

    float acc[2][8][4];
    #pragma unroll
    for (int mt = 0; mt < 2; mt++)
        #pragma unroll
        for (int nt = 0; nt < 8; nt++)
            #pragma unroll
            for (int q = 0; q < 4; q++) acc[mt][nt][q] = 0.f;

    const int nchunk = K >> 6;
    for (int ch = 0; ch < nchunk; ch++) {
        const int k0 = ch << 6;
        // ---- load+split A: 128 rows x 64 cols ----
        {
            int c4 = (tid & 15) * 4;
            int rb = tid >> 4;
            #pragma unroll
            for (int i = 0; i < 8; i++) {
                int r = rb + i * 16;
                int gr = row0 + r;
                float4 v = make_float4(0.f, 0.f, 0.f, 0.f);
                if (gr < M) v = *(const float4*)(A + (size_t)gr * K + k0 + c4);
                __nv_bfloat162 hA = __floats2bfloat162_rn(v.x, v.y);
                __nv_bfloat162 hB = __floats2bfloat162_rn(v.z, v.w);
                __nv_bfloat162 lA = __floats2bfloat162_rn(
                    v.x - __bfloat162float(hA.x), v.y - __bfloat162float(hA.y));
                __nv_bfloat162 lB = __floats2bfloat162_rn(
                    v.z - __bfloat162float(hB.x), v.w - __bfloat162float(hB.y));
                uint32_t off = (uint32_t)(r * (PITCH * 2) + c4 * 2);
                *(uint2*)(sm + OFF_AHI + off) =
                    make_uint2(*(uint32_t*)&hA, *(uint32_t*)&hB);
                *(uint2*)(sm + OFF_ALO + off) =
                    make_uint2(*(uint32_t*)&lA, *(uint32_t*)&lB);
            }
        }
        // ---- load+split B: W[k0..k0+63][n] -> Bs[n][k] ----
        {
            int n = tid >> 1;
            int kh = (tid & 1) * 32;
            #pragma unroll
            for (int kk = 0; kk < 32; kk += 2) {
                float v0 = W[(size_t)(k0 + kh + kk) * 128 + n];
                float v1 = W[(size_t)(k0 + kh + kk + 1) * 128 + n];
                __nv_bfloat162 h2 = __floats2bfloat162_rn(v0, v1);
                __nv_bfloat162 l2 = __floats2bfloat162_rn(
                    v0 - __bfloat162float(h2.x), v1 - __bfloat162float(h2.y));
                uint32_t off = (uint32_t)(n * (PITCH * 2) + (kh + kk) * 2);
                *(uint32_t*)(sm + OFF_BHI + off) = *(uint32_t*)&h2;
                *(uint32_t*)(sm + OFF_BLO + off) = *(uint32_t*)&l2;
            }
        }
        __syncthreads();

        // ---- compute: 4 k-steps of 16 ----
        #pragma unroll
        for (int ks = 0; ks < 4; ks++) {
            uint32_t ah[2][4], al[2][4];
            #pragma unroll
            for (int mt = 0; mt < 2; mt++) {
                uint32_t aoff = (uint32_t)(
                    (mr * 32 + mt * 16 + (lane & 15)) * (PITCH * 2)
                    + (ks * 16 + (lane >> 4) * 8) * 2);
                ldsm_x4(sb + OFF_AHI + aoff, ah[mt]);
                ldsm_x4(sb + OFF_ALO + aoff, al[mt]);
            }
            #pragma unroll
            for (int np = 0; np < 4; np++) {
                int n_idx = nc * 64 + np * 16 + (lane & 7) + ((lane >> 4) & 1) * 8;
                int koff = ks * 16 + ((lane >> 3) & 1) * 8;
                uint32_t boff = (uint32_t)(n_idx * (PITCH * 2) + koff * 2);
                uint32_t bh[4], bl[4];
                ldsm_x4(sb + OFF_BHI + boff, bh);
                ldsm_x4(sb + OFF_BLO + boff, bl);
                #pragma unroll
                for (int mt = 0; mt < 2; mt++) {
                    mma_bf16(acc[mt][np * 2],     ah[mt], bh);
                    mma_bf16(acc[mt][np * 2],     ah[mt], bl);
                    mma_bf16(acc[mt][np * 2],     al[mt], bh);
                    mma_bf16(acc[mt][np * 2 + 1], ah[mt], bh + 2);
                    mma_bf16(acc[mt][np * 2 + 1], ah[mt], bl + 2);
                    mma_bf16(acc[mt][np * 2 + 1], al[mt], bh + 2);
                }
            }
        }
        __syncthreads();
    }

    // ---- epilogue ----
    #pragma unroll
    for (int mt = 0; mt < 2; mt++) {
        int grA = row0 + mr * 32 + mt * 16 + g;
        int grB = grA + 8;
        if (mode == 0) {
            #pragma unroll
            for (int nt = 0; nt < 8; nt++) {
                int col = nc * 64 + nt * 8 + 2 * tg;
                float2 vA = make_float2(
                    fmaxf(acc[mt][nt][0] + sv0[col], 0.f),
                    fmaxf(acc[mt][nt][1] + sv0[col + 1], 0.f));
                float2 vB = make_float2(
                    fmaxf(acc[mt][nt][2] + sv0[col], 0.f),
                    fmaxf(acc[mt][nt][3] + sv0[col + 1], 0.f));
                if (grA < M) {
                    *(float2*)(C + (size_t)grA * 128 + col) = vA;
                    *(float2*)(Caux + (size_t)grA * 128 + col) = vA;
                }
                if (grB < M) {
                    *(float2*)(C + (size_t)grB * 128 + col) = vB;
                    *(float2*)(Caux + (size_t)grB * 128 + col) = vB;
                }
            }
        } else {
            float psA = 0.f, pdA = 0.f, psB = 0.f, pdB = 0.f;
            #pragma unroll
            for (int nt = 0; nt < 8; nt++) {
                int col = nc * 64 + nt * 8 + 2 * tg;
                float c0 = acc[mt][nt][0], c1 = acc[mt][nt][1];
                float c2 = acc[mt][nt][2], c3 = acc[mt][nt][3];
                float s0 = sv0[col], s1 = sv0[col + 1];
                float t0 = sv1[col], t1 = sv1[col + 1];
                psA += c0 * s0 + c1 * s1;
                pdA += c0 * t0 + c1 * t1;
                psB += c2 * s0 + c3 * s1;
                pdB += c2 * t0 + c3 * t1;
                if (grA < M) *(float2*)(C + (size_t)grA * 128 + col) = make_float2(c0, c1);
                if (grB < M) *(float2*)(C + (size_t)grB * 128 + col) = make_float2(c2, c3);
            }
            #pragma unroll
            for (int o = 1; o < 4; o <<= 1) {
                psA += __shfl_xor_sync(0xffffffffu, psA, o);
                pdA += __shfl_xor_sync(0xffffffffu, pdA, o);
                psB += __shfl_xor_sync(0xffffffffu, psB, o);
                pdB += __shfl_xor_sync(0xffffffffu, pdB, o);
            }
            if (tg == 0) {
                if (grA < M) {
                    as_out[grA * 2 + nc] = psA;
                    ad_out[grA * 2 + nc] = pdA;
                }
                if (grB < M) {
                    as_out[grB * 2 + nc] = psB;
                    ad_out[grB * 2 + nc] = pdB;
                }
            }
        }
    }
}

// ------------------------- per-dst aggregation (CSR, fused edge softmax) ----
__global__ __launch_bounds__(128) void agg_kernel(const float* __restrict__ bias) {
    int n = blockIdx.x;
    int t = threadIdx.x;
    int head = t >> 6;
    int start = d_rowstart[n], end = d_rowstart[n + 1];
    __shared__ int   s_src[128];
    __shared__ float s_w0[128];
    __shared__ float s_w1[128];
    const float2 adn = *(const float2*)&d_ad[n * 2];
    float acc = 0.f, wsum = 0.f;
    for (int base = start; base < end; base += 128) {
        int cnt = min(128, end - base);
        if (t < cnt) {
            int s = d_esrc[base + t];
            s_src[t] = s;
            float2 a = *(const float2*)&d_as[s * 2];
            float v0 = a.x + adn.x;
            float v1 = a.y + adn.y;
            v0 = v0 > 0.f ? v0 : 0.2f * v0;
            v1 = v1 > 0.f ? v1 : 0.2f * v1;
            s_w0[t] = __expf(v0);
            s_w1[t] = __expf(v1);
        }
        __syncthreads();
        for (int i = 0; i < cnt; i++) {
            int s = s_src[i];
            float w = head ? s_w1[i] : s_w0[i];
            acc += d_g[(size_t)s * HD + t] * w;
            wsum += w;
        }
        __syncthreads();
    }
    float out = acc / wsum + bias[t];
    out = fmaxf(out, 0.f);
    d_h[(size_t)n * HD + t] = out;
    d_hsum[(size_t)n * HD + t] += out;
}

// ------------------------- pooling (sorted batch) ---------------------------
__global__ __launch_bounds__(128) void pool_kernel(const int* __restrict__ batch) {
    const int CH = 256;
    int n0 = blockIdx.x * CH;
    int t = threadIdx.x;
    int nend = min(n0 + CH, N_NODES);
    int cnt = nend - n0;
    __shared__ int s_b[CH];
    for (int i = t; i < cnt; i += 128) s_b[i] = batch[n0 + i];
    __syncthreads();
    float acc = 0.f;
    int cur = s_b[0];
    for (int k = 0; k < cnt; k++) {
        int b = s_b[k];
        if (b != cur) {
            atomicAdd(&d_reprs[cur * HD + t], acc);
            acc = 0.f;
            cur = b;
        }
        acc += d_hsum[(size_t)(n0 + k) * HD + t];
    }
    atomicAdd(&d_reprs[cur * HD + t], acc);
}

// ------------------------- final MLP + log_softmax --------------------------
__global__ __launch_bounds__(128) void final_kernel(
    const float* __restrict__ W1, const float* __restrict__ b1,
    const float* __restrict__ W2, const float* __restrict__ b2,
    float* __restrict__ out)
{
    int g = blockIdx.x;
    int t = threadIdx.x;
    __shared__ float s_r[HD];
    __shared__ float s_z[HD];
    __shared__ float s_o[NCLS];
    s_r[t] = d_reprs[g * HD + t];
    __syncthreads();
    float acc = b1[t];
    #pragma unroll 4
    for (int k = 0; k < HD; k++) acc += s_r[k] * W1[k * HD + t];
    s_z[t] = fmaxf(acc, 0.f);
    __syncthreads();
    if (t < NCLS) {
        float a = b2[t];
        #pragma unroll 4
        for (int k = 0; k < HD; k++) a += s_z[k] * W2[k * NCLS + t];
        s_o[t] = a;
    }
    __syncthreads();
    if (t == 0) {
        float m = -1e30f;
        for (int c = 0; c < NCLS; c++) m = fmaxf(m, s_o[c]);
        float sum = 0.f;
        for (int c = 0; c < NCLS; c++) sum += expf(s_o[c] - m);
        float lse = m + logf(sum);
        for (int c = 0; c < NCLS; c++) out[g * NCLS + c] = s_o[c] - lse;
    }
}

// ------------------------- launch ------------------------------------------
extern "C" void kernel_launch(void* const* d_in, const int* in_sizes, int n_in,
                              void* d_out, int out_size)
{
    const float* x       = (const float*)d_in[0];
    const int*   ei      = (const int*)d_in[1];
    const int*   batch   = (const int*)d_in[2];
    const float* pre_w   = (const float*)d_in[3];
    const float* pre_b   = (const float*)d_in[4];
    const float* w1      = (const float*)d_in[5];
    const float* asrc1   = (const float*)d_in[6];
    const float* adst1   = (const float*)d_in[7];
    const float* b1      = (const float*)d_in[8];
    const float* w2      = (const float*)d_in[9];
    const float* asrc2   = (const float*)d_in[10];
    const float* adst2   = (const float*)d_in[11];
    const float* b2      = (const float*)d_in[12];
    const float* post_w1 = (const float*)d_in[13];
    const float* post_b1 = (const float*)d_in[14];
    const float* post_w2 = (const float*)d_in[15];
    const float* post_b2 = (const float*)d_in[16];
    float* out = (float*)d_out;

    void *p_h_, *p_g_, *p_hsum_, *p_as_, *p_ad_;
    cudaGetSymbolAddress(&p_h_, d_h);
    cudaGetSymbolAddress(&p_g_, d_g);
    cudaGetSymbolAddress(&p_hsum_, d_hsum);
    cudaGetSymbolAddress(&p_as_, d_as);
    cudaGetSymbolAddress(&p_ad_, d_ad);
    float* p_h = (float*)p_h_;
    float* p_g = (float*)p_g_;
    float* p_hsum = (float*)p_hsum_;
    float* p_as = (float*)p_as_;
    float* p_ad = (float*)p_ad_;

    cudaFuncSetAttribute(mma_gemm_kernel,
                         cudaFuncAttributeMaxDynamicSharedMemorySize, SMEM_DYN);

    const int TPB = 256;
    const int eblocks = (E_TOT + TPB - 1) / TPB;
    const int gb = (N_NODES + 127) / 128;

    zero_kernel<<<(N_NODES + TPB - 1) / TPB, TPB>>>();
    prep_hist_kernel<<<eblocks, TPB>>>(ei);
    scanA_kernel<<<NB_SCAN, 1024>>>();
    scanC_kernel<<<NB_SCAN, 1024>>>();
    scatter_kernel<<<eblocks, TPB>>>();

    // pre layer: h = relu(x@pre_w + pre_b); hsum = h
    mma_gemm_kernel<<<gb, 256, SMEM_DYN>>>(x, F_INPUT, pre_w, pre_b, nullptr,
                                           p_h, p_hsum, nullptr, nullptr,
                                           N_NODES, 0);

    // GAT layer 1
    mma_gemm_kernel<<<gb, 256, SMEM_DYN>>>(p_h, HD, w1, asrc1, adst1,
                                           p_g, nullptr, p_as, p_ad,
                                           N_NODES, 1);
    agg_kernel<<<N_NODES, 128>>>(b1);

    // GAT layer 2
    mma_gemm_kernel<<<gb, 256, SMEM_DYN>>>(p_h, HD, w2, asrc2, adst2,
                                           p_g, nullptr, p_as, p_ad,
                                           N_NODES, 1);
    agg_kernel<<<N_NODES, 128>>>(b2);

    // pooling + head
    pool_kernel<<<(N_NODES + 255) / 256, 128>>>(batch);
    final_kernel<<<G_GR, 128>>>(post_w1, post_b1, post_w2, post_b2, out);
}

// round 9
// speedup vs baseline: 2.4228x; 1.2124x over previous
#include <cuda_runtime.h>
#include <cuda_bf16.h>
#include <cstdint>

// ---------------------------------------------------------------------------
// GAT_25383256720122 : 2-layer GAT + pooling + MLP head.
// R8: warp-per-node aggregation (float4 lanes, shfl-broadcast edge meta,
//     no smem/syncs), prep deleted (hist+scatter read edge_index directly,
//     self-loops folded into deg init).
// ---------------------------------------------------------------------------

#define N_NODES 100000
#define E_EDGES 1600000
#define E_TOT   (E_EDGES + N_NODES)
#define F_INPUT 256
#define HD      128
#define G_GR    128
#define NCLS    10
#define NB_SCAN ((N_NODES + 1023) / 1024)   // 98

// ------------------------- device scratch ----------------------------------
__device__ float d_h[N_NODES * HD];
__device__ float d_g[N_NODES * HD];
__device__ float d_hsum[N_NODES * HD];
__device__ float d_as[N_NODES * 2];
__device__ float d_ad[N_NODES * 2];
__device__ int   d_esrc[E_TOT];          // CSR payload: src id per slot
__device__ int   d_deg[N_NODES];
__device__ int   d_rowstart[N_NODES + 1];
__device__ int   d_cursor[N_NODES];
__device__ float d_reprs[G_GR * HD];
__device__ int   d_bsum[NB_SCAN];

// ------------------------- helpers -----------------------------------------
__device__ __forceinline__ uint32_t smem_u32(const void* p) {
    uint32_t a;
    asm("{ .reg .u64 t; cvta.to.shared.u64 t, %1; cvt.u32.u64 %0, t; }"
        : "=r"(a) : "l"(p));
    return a;
}

__device__ __forceinline__ void ldsm_x4(uint32_t addr, uint32_t* r) {
    asm volatile("ldmatrix.sync.aligned.m8n8.x4.shared.b16 {%0,%1,%2,%3}, [%4];"
        : "=r"(r[0]), "=r"(r[1]), "=r"(r[2]), "=r"(r[3]) : "r"(addr));
}

__device__ __forceinline__ void mma_bf16(float* c, const uint32_t* a,
                                         const uint32_t* b) {
    asm volatile(
        "mma.sync.aligned.m16n8k16.row.col.f32.bf16.bf16.f32 "
        "{%0,%1,%2,%3}, {%4,%5,%6,%7}, {%8,%9}, {%0,%1,%2,%3};"
        : "+f"(c[0]), "+f"(c[1]), "+f"(c[2]), "+f"(c[3])
        : "r"(a[0]), "r"(a[1]), "r"(a[2]), "r"(a[3]), "r"(b[0]), "r"(b[1]));
}

// smem layout (bytes), pitch 72 bf16 = 144 B
#define PITCH    72
#define OFF_AHI  0
#define OFF_ALO  18432
#define OFF_BHI  36864
#define OFF_BLO  55296
#define OFF_V0   73728
#define OFF_V1   74240
#define SMEM_DYN 74752

// ------------------------- init: deg=1 (self-loop), reprs=0 ----------------
__global__ void zero_kernel() {
    int i = blockIdx.x * blockDim.x + threadIdx.x;
    if (i < N_NODES) d_deg[i] = 1;
    if (i < G_GR * HD) d_reprs[i] = 0.f;
}

__global__ void hist_kernel(const int* __restrict__ ei) {
    int i = blockIdx.x * blockDim.x + threadIdx.x;
    if (i < E_EDGES) atomicAdd(&d_deg[ei[E_EDGES + i]], 1);
}

// ------------------------- 2-phase scan ------------------------------------
__global__ __launch_bounds__(1024) void scanA_kernel() {
    __shared__ int ws[32];
    int tid = threadIdx.x, lane = tid & 31, wid = tid >> 5;
    int i = blockIdx.x * 1024 + tid;
    int v = (i < N_NODES) ? d_deg[i] : 0;
    #pragma unroll
    for (int o = 16; o > 0; o >>= 1) v += __shfl_down_sync(0xffffffffu, v, o);
    if (lane == 0) ws[wid] = v;
    __syncthreads();
    if (wid == 0) {
        int s = ws[lane];
        #pragma unroll
        for (int o = 16; o > 0; o >>= 1) s += __shfl_down_sync(0xffffffffu, s, o);
        if (lane == 0) d_bsum[blockIdx.x] = s;
    }
}

__global__ __launch_bounds__(1024) void scanC_kernel() {
    __shared__ int ws[32];
    __shared__ int s_off;
    int tid = threadIdx.x, lane = tid & 31, wid = tid >> 5;
    if (tid < 32) {
        int tot = 0;
        for (int j = tid; j < blockIdx.x; j += 32) tot += d_bsum[j];
        #pragma unroll
        for (int o = 16; o > 0; o >>= 1)
            tot += __shfl_down_sync(0xffffffffu, tot, o);
        if (tid == 0) s_off = tot;
    }
    int i = blockIdx.x * 1024 + tid;
    int v = (i < N_NODES) ? d_deg[i] : 0;
    int x = v;
    #pragma unroll
    for (int o = 1; o < 32; o <<= 1) {
        int y = __shfl_up_sync(0xffffffffu, x, o);
        if (lane >= o) x += y;
    }
    if (lane == 31) ws[wid] = x;
    __syncthreads();
    if (wid == 0) {
        int w = ws[lane];
        #pragma unroll
        for (int o = 1; o < 32; o <<= 1) {
            int y = __shfl_up_sync(0xffffffffu, w, o);
            if (lane >= o) w += y;
        }
        ws[lane] = w;
    }
    __syncthreads();
    int incl = x + (wid > 0 ? ws[wid - 1] : 0) + s_off;
    if (i < N_NODES) {
        d_rowstart[i + 1] = incl;
        d_cursor[i]       = incl - v;
    }
    if (i == 0) d_rowstart[0] = 0;
}

__global__ void scatter_kernel(const int* __restrict__ ei) {
    int i = blockIdx.x * blockDim.x + threadIdx.x;
    if (i < E_EDGES) {
        int s = ei[i], d = ei[E_EDGES + i];
        int p = atomicAdd(&d_cursor[d], 1);
        d_esrc[p] = s;
    } else if (i < E_TOT) {
        int n = i - E_EDGES;
        int p = atomicAdd(&d_cursor[n], 1);
        d_esrc[p] = n;
    }
}

// ------------------------- mma.sync GEMM -----------------------------------
// C[M,128] = A[M,K] @ W[K,128], bf16 hi/lo split (3 mma terms).
// mode 0: C = relu(A@W + vec0), Caux = C.
// mode 1: C = A@W raw; fused alpha dots: as_out/ad_out [M,2].
__global__ __launch_bounds__(256) void mma_gemm_kernel(
    const float* __restrict__ A, int K,
    const float* __restrict__ W,
    const float* __restrict__ vec0, const float* __restrict__ vec1,
    float* __restrict__ C, float* __restrict__ Caux,
    float* __restrict__ as_out, float* __restrict__ ad_out,
    int M, int mode)
{
    extern __shared__ char sm[];
    const uint32_t sb = smem_u32(sm);
    float* sv0 = (float*)(sm + OFF_V0);
    float* sv1 = (float*)(sm + OFF_V1);

    const int tid = threadIdx.x;
    const int w = tid >> 5;
    const int lane = tid & 31;
    const int mr = w >> 1;          // 0..3 : warp M-row
    const int nc = w & 1;           // 0..1 : warp N-col (== attention head)
    const int row0 = blockIdx.x * 128;
    const int g = lane >> 2, tg = lane & 3;

    if (tid < 128) {
        sv0[tid] = vec0 ? vec0[tid] : 0.f;
        sv1[tid] = vec1 ? vec1[tid] : 0.f;
    }

    float acc[2][8][4];
    #pragma unroll
    for (int mt = 0; mt < 2; mt++)
        #pragma unroll
        for (int nt = 0; nt < 8; nt++)
            #pragma unroll
            for (int q = 0; q < 4; q++) acc[mt][nt][q] = 0.f;

    const int nchunk = K >> 6;
    for (int ch = 0; ch < nchunk; ch++) {
        const int k0 = ch << 6;
        // ---- load+split A: 128 rows x 64 cols ----
        {
            int c4 = (tid & 15) * 4;
            int rb = tid >> 4;
            #pragma unroll
            for (int i = 0; i < 8; i++) {
                int r = rb + i * 16;
                int gr = row0 + r;
                float4 v = make_float4(0.f, 0.f, 0.f, 0.f);
                if (gr < M) v = *(const float4*)(A + (size_t)gr * K + k0 + c4);
                __nv_bfloat162 hA = __floats2bfloat162_rn(v.x, v.y);
                __nv_bfloat162 hB = __floats2bfloat162_rn(v.z, v.w);
                __nv_bfloat162 lA = __floats2bfloat162_rn(
                    v.x - __bfloat162float(hA.x), v.y - __bfloat162float(hA.y));
                __nv_bfloat162 lB = __floats2bfloat162_rn(
                    v.z - __bfloat162float(hB.x), v.w - __bfloat162float(hB.y));
                uint32_t off = (uint32_t)(r * (PITCH * 2) + c4 * 2);
                *(uint2*)(sm + OFF_AHI + off) =
                    make_uint2(*(uint32_t*)&hA, *(uint32_t*)&hB);
                *(uint2*)(sm + OFF_ALO + off) =
                    make_uint2(*(uint32_t*)&lA, *(uint32_t*)&lB);
            }
        }
        // ---- load+split B: W[k0..k0+63][n] -> Bs[n][k] ----
        {
            int n = tid >> 1;
            int kh = (tid & 1) * 32;
            #pragma unroll
            for (int kk = 0; kk < 32; kk += 2) {
                float v0 = W[(size_t)(k0 + kh + kk) * 128 + n];
                float v1 = W[(size_t)(k0 + kh + kk + 1) * 128 + n];
                __nv_bfloat162 h2 = __floats2bfloat162_rn(v0, v1);
                __nv_bfloat162 l2 = __floats2bfloat162_rn(
                    v0 - __bfloat162float(h2.x), v1 - __bfloat162float(h2.y));
                uint32_t off = (uint32_t)(n * (PITCH * 2) + (kh + kk) * 2);
                *(uint32_t*)(sm + OFF_BHI + off) = *(uint32_t*)&h2;
                *(uint32_t*)(sm + OFF_BLO + off) = *(uint32_t*)&l2;
            }
        }
        __syncthreads();

        // ---- compute: 4 k-steps of 16 ----
        #pragma unroll
        for (int ks = 0; ks < 4; ks++) {
            uint32_t ah[2][4], al[2][4];
            #pragma unroll
            for (int mt = 0; mt < 2; mt++) {
                uint32_t aoff = (uint32_t)(
                    (mr * 32 + mt * 16 + (lane & 15)) * (PITCH * 2)
                    + (ks * 16 + (lane >> 4) * 8) * 2);
                ldsm_x4(sb + OFF_AHI + aoff, ah[mt]);
                ldsm_x4(sb + OFF_ALO + aoff, al[mt]);
            }
            #pragma unroll
            for (int np = 0; np < 4; np++) {
                int n_idx = nc * 64 + np * 16 + (lane & 7) + ((lane >> 4) & 1) * 8;
                int koff = ks * 16 + ((lane >> 3) & 1) * 8;
                uint32_t boff = (uint32_t)(n_idx * (PITCH * 2) + koff * 2);
                uint32_t bh[4], bl[4];
                ldsm_x4(sb + OFF_BHI + boff, bh);
                ldsm_x4(sb + OFF_BLO + boff, bl);
                #pragma unroll
                for (int mt = 0; mt < 2; mt++) {
                    mma_bf16(acc[mt][np * 2],     ah[mt], bh);
                    mma_bf16(acc[mt][np * 2],     ah[mt], bl);
                    mma_bf16(acc[mt][np * 2],     al[mt], bh);
                    mma_bf16(acc[mt][np * 2 + 1], ah[mt], bh + 2);
                    mma_bf16(acc[mt][np * 2 + 1], ah[mt], bl + 2);
                    mma_bf16(acc[mt][np * 2 + 1], al[mt], bh + 2);
                }
            }
        }
        __syncthreads();
    }

    // ---- epilogue ----
    #pragma unroll
    for (int mt = 0; mt < 2; mt++) {
        int grA = row0 + mr * 32 + mt * 16 + g;
        int grB = grA + 8;
        if (mode == 0) {
            #pragma unroll
            for (int nt = 0; nt < 8; nt++) {
                int col = nc * 64 + nt * 8 + 2 * tg;
                float2 vA = make_float2(
                    fmaxf(acc[mt][nt][0] + sv0[col], 0.f),
                    fmaxf(acc[mt][nt][1] + sv0[col + 1], 0.f));
                float2 vB = make_float2(
                    fmaxf(acc[mt][nt][2] + sv0[col], 0.f),
                    fmaxf(acc[mt][nt][3] + sv0[col + 1], 0.f));
                if (grA < M) {
                    *(float2*)(C + (size_t)grA * 128 + col) = vA;
                    *(float2*)(Caux + (size_t)grA * 128 + col) = vA;
                }
                if (grB < M) {
                    *(float2*)(C + (size_t)grB * 128 + col) = vB;
                    *(float2*)(Caux + (size_t)grB * 128 + col) = vB;
                }
            }
        } else {
            float psA = 0.f, pdA = 0.f, psB = 0.f, pdB = 0.f;
            #pragma unroll
            for (int nt = 0; nt < 8; nt++) {
                int col = nc * 64 + nt * 8 + 2 * tg;
                float c0 = acc[mt][nt][0], c1 = acc[mt][nt][1];
                float c2 = acc[mt][nt][2], c3 = acc[mt][nt][3];
                float s0 = sv0[col], s1 = sv0[col + 1];
                float t0 = sv1[col], t1 = sv1[col + 1];
                psA += c0 * s0 + c1 * s1;
                pdA += c0 * t0 + c1 * t1;
                psB += c2 * s0 + c3 * s1;
                pdB += c2 * t0 + c3 * t1;
                if (grA < M) *(float2*)(C + (size_t)grA * 128 + col) = make_float2(c0, c1);
                if (grB < M) *(float2*)(C + (size_t)grB * 128 + col) = make_float2(c2, c3);
            }
            #pragma unroll
            for (int o = 1; o < 4; o <<= 1) {
                psA += __shfl_xor_sync(0xffffffffu, psA, o);
                pdA += __shfl_xor_sync(0xffffffffu, pdA, o);
                psB += __shfl_xor_sync(0xffffffffu, psB, o);
                pdB += __shfl_xor_sync(0xffffffffu, pdB, o);
            }
            if (tg == 0) {
                if (grA < M) {
                    as_out[grA * 2 + nc] = psA;
                    ad_out[grA * 2 + nc] = pdA;
                }
                if (grB < M) {
                    as_out[grB * 2 + nc] = psB;
                    ad_out[grB * 2 + nc] = pdB;
                }
            }
        }
    }
}

// ------------------------- warp-per-node aggregation ------------------------
// Warp owns node n; lane owns cols 4*lane..4*lane+3 (head = lane>>4).
// Edge meta (src, exp-weights) computed 32-at-a-time, broadcast via shfl.
__global__ __launch_bounds__(128) void agg_kernel(const float* __restrict__ bias) {
    int n = blockIdx.x * 4 + (threadIdx.x >> 5);
    if (n >= N_NODES) return;
    const int lane = threadIdx.x & 31;
    const int start = d_rowstart[n], end = d_rowstart[n + 1];
    const float2 adn = *(const float2*)&d_ad[n * 2];
    const bool head1 = (lane >= 16);

    float4 acc = make_float4(0.f, 0.f, 0.f, 0.f);
    float wsum = 0.f;

    for (int base = start; base < end; base += 32) {
        int cnt = min(32, end - base);
        int s = 0;
        float w0 = 0.f, w1 = 0.f;
        if (lane < cnt) {
            s = d_esrc[base + lane];
            float2 a = *(const float2*)&d_as[s * 2];
            float v0 = a.x + adn.x;
            float v1 = a.y + adn.y;
            v0 = v0 > 0.f ? v0 : 0.2f * v0;
            v1 = v1 > 0.f ? v1 : 0.2f * v1;
            w0 = __expf(v0);
            w1 = __expf(v1);
        }
        #pragma unroll 4
        for (int i = 0; i < cnt; i++) {
            int   si  = __shfl_sync(0xffffffffu, s,  i);
            float w0i = __shfl_sync(0xffffffffu, w0, i);
            float w1i = __shfl_sync(0xffffffffu, w1, i);
            float wi = head1 ? w1i : w0i;
            float4 gv = *(const float4*)&d_g[(size_t)si * HD + lane * 4];
            acc.x += gv.x * wi;
            acc.y += gv.y * wi;
            acc.z += gv.z * wi;
            acc.w += gv.w * wi;
            wsum  += wi;
        }
    }
    float inv = 1.f / wsum;
    float4 bv = *(const float4*)&bias[lane * 4];
    float4 out;
    out.x = fmaxf(acc.x * inv + bv.x, 0.f);
    out.y = fmaxf(acc.y * inv + bv.y, 0.f);
    out.z = fmaxf(acc.z * inv + bv.z, 0.f);
    out.w = fmaxf(acc.w * inv + bv.w, 0.f);
    size_t o = (size_t)n * HD + lane * 4;
    *(float4*)&d_h[o] = out;
    float4 hs = *(const float4*)&d_hsum[o];
    hs.x += out.x; hs.y += out.y; hs.z += out.z; hs.w += out.w;
    *(float4*)&d_hsum[o] = hs;
}

// ------------------------- pooling (sorted batch) ---------------------------
__global__ __launch_bounds__(128) void pool_kernel(const int* __restrict__ batch) {
    const int CH = 256;
    int n0 = blockIdx.x * CH;
    int t = threadIdx.x;
    int nend = min(n0 + CH, N_NODES);
    int cnt = nend - n0;
    __shared__ int s_b[CH];
    for (int i = t; i < cnt; i += 128) s_b[i] = batch[n0 + i];
    __syncthreads();
    float acc = 0.f;
    int cur = s_b[0];
    for (int k = 0; k < cnt; k++) {
        int b = s_b[k];
        if (b != cur) {
            atomicAdd(&d_reprs[cur * HD + t], acc);
            acc = 0.f;
            cur = b;
        }
        acc += d_hsum[(size_t)(n0 + k) * HD + t];
    }
    atomicAdd(&d_reprs[cur * HD + t], acc);
}

// ------------------------- final MLP + log_softmax --------------------------
__global__ __launch_bounds__(128) void final_kernel(
    const float* __restrict__ W1, const float* __restrict__ b1,
    const float* __restrict__ W2, const float* __restrict__ b2,
    float* __restrict__ out)
{
    int g = blockIdx.x;
    int t = threadIdx.x;
    __shared__ float s_r[HD];
    __shared__ float s_z[HD];
    __shared__ float s_o[NCLS];
    s_r[t] = d_reprs[g * HD + t];
    __syncthreads();
    float acc = b1[t];
    #pragma unroll 4
    for (int k = 0; k < HD; k++) acc += s_r[k] * W1[k * HD + t];
    s_z[t] = fmaxf(acc, 0.f);
    __syncthreads();
    if (t < NCLS) {
        float a = b2[t];
        #pragma unroll 4
        for (int k = 0; k < HD; k++) a += s_z[k] * W2[k * NCLS + t];
        s_o[t] = a;
    }
    __syncthreads();
    if (t == 0) {
        float m = -1e30f;
        for (int c = 0; c < NCLS; c++) m = fmaxf(m, s_o[c]);
        float sum = 0.f;
        for (int c = 0; c < NCLS; c++) sum += expf(s_o[c] - m);
        float lse = m + logf(sum);
        for (int c = 0; c < NCLS; c++) out[g * NCLS + c] = s_o[c] - lse;
    }
}

// ------------------------- launch ------------------------------------------
extern "C" void kernel_launch(void* const* d_in, const int* in_sizes, int n_in,
                              void* d_out, int out_size)
{
    const float* x       = (const float*)d_in[0];
    const int*   ei      = (const int*)d_in[1];
    const int*   batch   = (const int*)d_in[2];
    const float* pre_w   = (const float*)d_in[3];
    const float* pre_b   = (const float*)d_in[4];
    const float* w1      = (const float*)d_in[5];
    const float* asrc1   = (const float*)d_in[6];
    const float* adst1   = (const float*)d_in[7];
    const float* b1      = (const float*)d_in[8];
    const float* w2      = (const float*)d_in[9];
    const float* asrc2   = (const float*)d_in[10];
    const float* adst2   = (const float*)d_in[11];
    const float* b2      = (const float*)d_in[12];
    const float* post_w1 = (const float*)d_in[13];
    const float* post_b1 = (const float*)d_in[14];
    const float* post_w2 = (const float*)d_in[15];
    const float* post_b2 = (const float*)d_in[16];
    float* out = (float*)d_out;

    void *p_h_, *p_g_, *p_hsum_, *p_as_, *p_ad_;
    cudaGetSymbolAddress(&p_h_, d_h);
    cudaGetSymbolAddress(&p_g_, d_g);
    cudaGetSymbolAddress(&p_hsum_, d_hsum);
    cudaGetSymbolAddress(&p_as_, d_as);
    cudaGetSymbolAddress(&p_ad_, d_ad);
    float* p_h = (float*)p_h_;
    float* p_g = (float*)p_g_;
    float* p_hsum = (float*)p_hsum_;
    float* p_as = (float*)p_as_;
    float* p_ad = (float*)p_ad_;

    cudaFuncSetAttribute(mma_gemm_kernel,
                         cudaFuncAttributeMaxDynamicSharedMemorySize, SMEM_DYN);

    const int TPB = 256;
    const int eblocks = (E_TOT + TPB - 1) / TPB;
    const int gb = (N_NODES + 127) / 128;

    zero_kernel<<<(N_NODES + TPB - 1) / TPB, TPB>>>();
    hist_kernel<<<(E_EDGES + TPB - 1) / TPB, TPB>>>(ei);
    scanA_kernel<<<NB_SCAN, 1024>>>();
    scanC_kernel<<<NB_SCAN, 1024>>>();
    scatter_kernel<<<eblocks, TPB>>>(ei);

    // pre layer: h = relu(x@pre_w + pre_b); hsum = h
    mma_gemm_kernel<<<gb, 256, SMEM_DYN>>>(x, F_INPUT, pre_w, pre_b, nullptr,
                                           p_h, p_hsum, nullptr, nullptr,
                                           N_NODES, 0);

    // GAT layer 1
    mma_gemm_kernel<<<gb, 256, SMEM_DYN>>>(p_h, HD, w1, asrc1, adst1,
                                           p_g, nullptr, p_as, p_ad,
                                           N_NODES, 1);
    agg_kernel<<<(N_NODES + 3) / 4, 128>>>(b1);

    // GAT layer 2
    mma_gemm_kernel<<<gb, 256, SMEM_DYN>>>(p_h, HD, w2, asrc2, adst2,
                                           p_g, nullptr, p_as, p_ad,
                                           N_NODES, 1);
    agg_kernel<<<(N_NODES + 3) / 4, 128>>>(b2);

    // pooling + head
    pool_kernel<<<(N_NODES + 255) / 256, 128>>>(batch);
    final_kernel<<<G_GR, 128>>>(post_w1, post_b1, post_w2, post_b2, out);
}